// round 15
// baseline (speedup 1.0000x reference)
#include <cuda_runtime.h>
#include <cuda_bf16.h>
#include <stdint.h>
#include <math.h>

#define Bn 2048
#define N0 289
#define N1 100
#define N2 25
#define NSWEEP 4
#define EPSV 1e-6f
#define KTILES 20
#define NTILES 13
#define KT2 20
#define MT2 7

// ---------------- scratch ----------------
__device__ __align__(16) uint2 g_Wfrag[2 * KTILES * NTILES * 32];
__device__ __align__(16) uint4 g_Waf[2 * MT2 * KT2 * 32];
__device__ __align__(16) uint2 g_T1f[(size_t)2 * Bn * KT2 * NTILES * 32];
__device__ float g_Y2[Bn * N2 * N2];

// ---------------- helpers ----------------
static __device__ __forceinline__ void cpa4p(float* smem_dst, const float* gsrc, bool valid) {
    unsigned d = (unsigned)__cvta_generic_to_shared(smem_dst);
    unsigned sz = valid ? 4u : 0u;
    asm volatile("cp.async.ca.shared.global [%0], [%1], 4, %2;" :: "r"(d), "l"(gsrc), "r"(sz));
}
static __device__ __forceinline__ void cpa16(void* smem_dst, const void* gsrc) {
    unsigned d = (unsigned)__cvta_generic_to_shared(smem_dst);
    asm volatile("cp.async.cg.shared.global [%0], [%1], 16;" :: "r"(d), "l"(gsrc));
}
static __device__ __forceinline__ void cpa_commit() { asm volatile("cp.async.commit_group;"); }
static __device__ __forceinline__ void cpa_wait0() { asm volatile("cp.async.wait_group 0;"); }
static __device__ __forceinline__ void cpa_wait1() { asm volatile("cp.async.wait_group 1;"); }
static __device__ __forceinline__ void cpa_wait2() { asm volatile("cp.async.wait_group 2;"); }
static __device__ __forceinline__ float fsinh(float x) {
    float e = __expf(x), ei = __expf(-x);
    return 0.5f * (e - ei);
}
static __device__ __forceinline__ void mma_bf16(float* c, const unsigned* a, uint2 b) {
    asm volatile(
        "mma.sync.aligned.m16n8k16.row.col.f32.bf16.bf16.f32 "
        "{%0,%1,%2,%3}, {%4,%5,%6,%7}, {%8,%9}, {%0,%1,%2,%3};"
        : "+f"(c[0]), "+f"(c[1]), "+f"(c[2]), "+f"(c[3])
        : "r"(a[0]), "r"(a[1]), "r"(a[2]), "r"(a[3]), "r"(b.x), "r"(b.y));
}
static __device__ __forceinline__ void ldm_x4(unsigned* r, unsigned saddr) {
    asm volatile("ldmatrix.sync.aligned.m8n8.x4.shared.b16 {%0,%1,%2,%3}, [%4];"
                 : "=r"(r[0]), "=r"(r[1]), "=r"(r[2]), "=r"(r[3]) : "r"(saddr));
}

// ---------------- K0a: K1 B-fragments ----------------
__global__ void k0_wfrag(const float* __restrict__ W1) {
    int i = blockIdx.x * blockDim.x + threadIdx.x;
    if (i >= 2 * KTILES * NTILES * 32) return;
    int lane = i & 31;
    int rest = i >> 5;
    int nt = rest % NTILES; rest /= NTILES;
    int kt = rest % KTILES;
    int ver = rest / KTILES;
    int g = lane >> 2, t = lane & 3;
    int n = nt * 8 + g, k0 = kt * 16;
    float v[4];
#pragma unroll
    for (int j = 0; j < 4; j++) {
        int k = k0 + 2 * t + (j & 1) + (j >> 1) * 8;
        v[j] = (n < N1 && k < N0) ? W1[n * N0 + k] : 0.f;
    }
    __nv_bfloat16 o[4];
#pragma unroll
    for (int j = 0; j < 4; j++) {
        __nv_bfloat16 h = __float2bfloat16(v[j]);
        o[j] = (ver == 0) ? h : __float2bfloat16(v[j] - __bfloat162float(h));
    }
    __nv_bfloat162 r0; r0.x = o[0]; r0.y = o[1];
    __nv_bfloat162 r1; r1.x = o[2]; r1.y = o[3];
    uint2 out;
    out.x = *(unsigned*)&r0;
    out.y = *(unsigned*)&r1;
    g_Wfrag[i] = out;
}

// ---------------- K0b: K2 A-fragments ----------------
__global__ void k0_wafrag(const float* __restrict__ W1) {
    int i = blockIdx.x * blockDim.x + threadIdx.x;
    if (i >= 2 * MT2 * KT2 * 32) return;
    int lane = i & 31;
    int rest = i >> 5;
    int kt = rest % KT2; rest /= KT2;
    int mt = rest % MT2;
    int ver = rest / MT2;
    int g = lane >> 2, t = lane & 3;
    int m0 = mt * 16 + g, m1 = m0 + 8;
    int k0 = kt * 16 + 2 * t;
    float e[4][2];
#pragma unroll
    for (int reg = 0; reg < 4; reg++) {
        int m = (reg & 1) ? m1 : m0;
        int kb = k0 + ((reg >> 1) ? 8 : 0);
#pragma unroll
        for (int j = 0; j < 2; j++) {
            int k = kb + j;
            e[reg][j] = (m < N1 && k < N0) ? W1[m * N0 + k] : 0.f;
        }
    }
    unsigned r[4];
#pragma unroll
    for (int reg = 0; reg < 4; reg++) {
        __nv_bfloat16 b0 = __float2bfloat16(e[reg][0]);
        __nv_bfloat16 b1 = __float2bfloat16(e[reg][1]);
        if (ver == 1) {
            b0 = __float2bfloat16(e[reg][0] - __bfloat162float(b0));
            b1 = __float2bfloat16(e[reg][1] - __bfloat162float(b1));
        }
        __nv_bfloat162 p; p.x = b0; p.y = b1;
        r[reg] = *(unsigned*)&p;
    }
    uint4 out; out.x = r[0]; out.y = r[1]; out.z = r[2]; out.w = r[3];
    g_Waf[((size_t)(ver * MT2 + mt) * KT2 + kt) * 32 + lane] = out;
}

// tiny dummy to keep ncu's capture slot on k1
__global__ void k_dummy() {
    if (blockIdx.x == 0 && threadIdx.x == 0) g_Y2[0] = 0.f;
}

// ---------------- K1: T1[b] = X[b] @ W1^T via HMMA; B staged 1 ahead, X 2 ahead ----------------
// dynamic smem layout (bytes):
//   [0      .. 20480)  AH[2][128*40] bf16
//   [20480  .. 40960)  AL[2][128*40] bf16
//   [40960  .. 73728)  Xf[2][128*32] f32   (epilogue: Tb bf16 [128*104])
//   [73728  .. 100352) Bs[2][2ver][2kt][13nt][32lane] uint2
#define K1_SMEM 100352

__global__ void __launch_bounds__(256, 2) k1_hmma(const float* __restrict__ X) {
    extern __shared__ char sm1[];
    __nv_bfloat16* AHb = (__nv_bfloat16*)sm1;
    __nv_bfloat16* ALb = (__nv_bfloat16*)(sm1 + 20480);
    float* XfTb = (float*)(sm1 + 40960);
    __nv_bfloat16* Tb = (__nv_bfloat16*)XfTb;
    uint2* Bs = (uint2*)(sm1 + 73728);

    const int tid = threadIdx.x, w = tid >> 5, lane = tid & 31;
    const int g = lane >> 2, t = lane & 3;
    const int b = blockIdx.y, m0 = blockIdx.x * 128;
    const float* Xb = X + (size_t)b * N0 * N0;

    const int mg = (w & 3) * 32;
    const int nh = w >> 2;
    const int ntbase = nh ? 7 : 0;
    const int ntcnt = nh ? 6 : 7;
    const bool act = (m0 + mg) < N0;

    float acc[2][7][4];
#pragma unroll
    for (int a = 0; a < 2; a++)
#pragma unroll
        for (int n = 0; n < 7; n++)
#pragma unroll
            for (int c = 0; c < 4; c++) acc[a][n][c] = 0.f;

    // stage X chunk c (own commit group)
    auto stageX = [&](int c) {
        float* xf = XfTb + (c & 1) * 4096;
#pragma unroll
        for (int i = 0; i < 16; i++) {
            int e = tid + i * 256;
            int row = e >> 5, col = e & 31;
            int m = m0 + row, k = c * 32 + col;
            bool v = (m < N0) && (k < N0);
            cpa4p(xf + e, Xb + (v ? ((size_t)m * N0 + k) : 0), v);
        }
        cpa_commit();
    };
    // stage B fragments for chunk c (own commit group) — only 1 ahead of compute
    auto stageB = [&](int c) {
        const int buf = c & 1;
#pragma unroll
        for (int i = 0; i < 4; i++) {
            int u = tid + i * 256;
            if (u < 832) {
                int verkt = u / 208, o = u - verkt * 208;   // o in 16B units
                int ver = verkt >> 1, ktl = verkt & 1;
                int ktg = 2 * c + ktl;
                uint2* dst = Bs + ((buf * 2 + ver) * 2 + ktl) * 416 + o * 2;
                const uint2* src = g_Wfrag + ((ver * KTILES + ktg) * NTILES) * 32 + o * 2;
                cpa16(dst, src);
            }
        }
        cpa_commit();
    };
    auto convert = [&](int c) {
        const float* xf = XfTb + (c & 1) * 4096;
        __nv_bfloat16* ah = AHb + (c & 1) * 5120;
        __nv_bfloat16* al = ALb + (c & 1) * 5120;
#pragma unroll
        for (int i = 0; i < 4; i++) {
            int e4 = tid + i * 256;
            int row = e4 >> 3, q = e4 & 7;
            float4 v = *(const float4*)(xf + row * 32 + q * 4);
            unsigned bx = __float_as_uint(v.x), by = __float_as_uint(v.y);
            unsigned bz = __float_as_uint(v.z), bw = __float_as_uint(v.w);
            unsigned h01 = __byte_perm(bx, by, 0x7632);
            unsigned h23 = __byte_perm(bz, bw, 0x7632);
            float lx = v.x - __uint_as_float(bx & 0xFFFF0000u);
            float ly = v.y - __uint_as_float(by & 0xFFFF0000u);
            float lz = v.z - __uint_as_float(bz & 0xFFFF0000u);
            float lw = v.w - __uint_as_float(bw & 0xFFFF0000u);
            unsigned l01, l23;
            asm("cvt.rn.bf16x2.f32 %0, %1, %2;" : "=r"(l01) : "f"(ly), "f"(lx));
            asm("cvt.rn.bf16x2.f32 %0, %1, %2;" : "=r"(l23) : "f"(lw), "f"(lz));
            uint2 sh; sh.x = h01; sh.y = h23;
            uint2 sl; sl.x = l01; sl.y = l23;
            *(uint2*)(ah + row * 40 + q * 4) = sh;
            *(uint2*)(al + row * 40 + q * 4) = sl;
        }
    };
    auto compute = [&](int c) {
        if (!act) return;
        const int buf = c & 1;
        unsigned ahbase = (unsigned)__cvta_generic_to_shared(AHb + buf * 5120);
        unsigned albase = (unsigned)__cvta_generic_to_shared(ALb + buf * 5120);
        const int lrow = lane & 15, lkof = (lane >> 4) * 16;
#pragma unroll
        for (int kt = 0; kt < 2; kt++) {
            if (c == 9 && kt == 1) break;
            const int kb = kt * 32 + lkof;
            unsigned ah[2][4], al[2][4];
#pragma unroll
            for (int mt = 0; mt < 2; mt++) {
                unsigned roff = (unsigned)((mg + mt * 16 + lrow) * 80 + kb);
                ldm_x4(ah[mt], ahbase + roff);
                ldm_x4(al[mt], albase + roff);
            }
            const uint2* bhb = Bs + ((buf * 2 + 0) * 2 + kt) * 416 + ntbase * 32 + lane;
            const uint2* blb = Bs + ((buf * 2 + 1) * 2 + kt) * 416 + ntbase * 32 + lane;
#pragma unroll
            for (int nt = 0; nt < 7; nt++) {
                if (nt >= ntcnt) break;
                uint2 bh = bhb[nt * 32];
                uint2 bl = blb[nt * 32];
#pragma unroll
                for (int mt = 0; mt < 2; mt++) {
                    mma_bf16(acc[mt][nt], ah[mt], bh);
                    mma_bf16(acc[mt][nt], ah[mt], bl);
                    mma_bf16(acc[mt][nt], al[mt], bh);
                }
            }
        }
    };

    // prologue: groups X0, B0, X1 in flight; need X0 for convert(0)
    stageX(0);
    stageB(0);
    stageX(1);
    cpa_wait2();          // X0 complete (B0, X1 may be pending)
    __syncthreads();
    convert(0);
    __syncthreads();

    for (int c = 0; c < 10; c++) {
        if (c + 1 < 10) stageB(c + 1);
        if (c + 2 < 10) stageX(c + 2);
        // guarantee B(c) and X(c+1) complete; keep only this iter's groups pending
        if (c <= 7) cpa_wait2();
        else if (c == 8) cpa_wait1();
        else cpa_wait0();
        __syncthreads();
        if (c + 1 < 10) convert(c + 1);
        compute(c);
        __syncthreads();
    }

    // ---- epilogue: emit T1 bf16 hi/lo fragments ----
#pragma unroll
    for (int v = 0; v < 2; v++) {
#pragma unroll
        for (int mt = 0; mt < 2; mt++) {
#pragma unroll
            for (int nt = 0; nt < 7; nt++) {
                if (nt >= ntcnt) break;
                int r = mg + mt * 16 + g;
                int cc = (ntbase + nt) * 8 + 2 * t;
                float a0 = acc[mt][nt][0], a1 = acc[mt][nt][1];
                float a2 = acc[mt][nt][2], a3 = acc[mt][nt][3];
                __nv_bfloat16 h0 = __float2bfloat16(a0), h1 = __float2bfloat16(a1);
                __nv_bfloat16 h2 = __float2bfloat16(a2), h3 = __float2bfloat16(a3);
                if (v == 1) {
                    h0 = __float2bfloat16(a0 - __bfloat162float(h0));
                    h1 = __float2bfloat16(a1 - __bfloat162float(h1));
                    h2 = __float2bfloat16(a2 - __bfloat162float(h2));
                    h3 = __float2bfloat16(a3 - __bfloat162float(h3));
                }
                __nv_bfloat162 p0; p0.x = h0; p0.y = h1;
                __nv_bfloat162 p1; p1.x = h2; p1.y = h3;
                *(__nv_bfloat162*)(Tb + r * 104 + cc) = p0;
                *(__nv_bfloat162*)(Tb + (r + 8) * 104 + cc) = p1;
            }
        }
        __syncthreads();
        for (int idx = tid; idx < 8 * 13 * 32; idx += 256) {
            int lane2 = idx & 31;
            int q = idx >> 5;
            int nt2 = q % 13, ktl = q / 13;
            int ktg = (m0 >> 4) + ktl;
            if (ktg < KT2) {
                int g2 = lane2 >> 2, t2 = lane2 & 3;
                int kr = ktl * 16 + 2 * t2, n = nt2 * 8 + g2;
                __nv_bfloat162 q0, q1;
                q0.x = Tb[kr * 104 + n];
                q0.y = Tb[(kr + 1) * 104 + n];
                q1.x = Tb[(kr + 8) * 104 + n];
                q1.y = Tb[(kr + 9) * 104 + n];
                uint2 val;
                val.x = *(unsigned*)&q0;
                val.y = *(unsigned*)&q1;
                g_T1f[(((size_t)v * Bn + b) * KT2 + ktg) * 416 + nt2 * 32 + lane2] = val;
            }
        }
        __syncthreads();
    }
}

// ---------------- K2: Y1 = sinh(W1 @ T1) via HMMA; then W2 bimaps + sinh ----------------
__global__ void __launch_bounds__(224, 2) k2_hmma(const float* __restrict__ W2) {
    extern __shared__ char smc[];
    uint2* Bf = (uint2*)smc;
    float* W2s = (float*)(smc + 26624);
    float* Y1s = W2s + 2500;
    float* T2t = Y1s + 10400;

    const int tid = threadIdx.x, w = tid >> 5, lane = tid & 31;
    const int g = lane >> 2, t = lane & 3;
    const int b = blockIdx.x;

    for (int i = tid; i < N2 * N1; i += 224) W2s[i] = W2[i];

    auto stage = [&](int c, int buf) {
        for (int u = tid; u < 832; u += 224) {
            int ver = u / 416;
            int r = u - ver * 416;
            int ktl = r / 208;
            int o = r - ktl * 208;
            uint2* dst = Bf + ((buf * 2 + ver) * 2 + ktl) * 416 + o * 2;
            const uint2* src = g_T1f + (((size_t)ver * Bn + b) * KT2 + c * 2 + ktl) * 416 + o * 2;
            cpa16(dst, src);
        }
        cpa_commit();
    };

    float acc[13][4];
#pragma unroll
    for (int n = 0; n < 13; n++)
#pragma unroll
        for (int c = 0; c < 4; c++) acc[n][c] = 0.f;

    stage(0, 0);
    cpa_wait0();
    __syncthreads();

    for (int c = 0; c < 10; c++) {
        if (c < 9) stage(c + 1, (c + 1) & 1);
        const int cur = c & 1;
#pragma unroll
        for (int ktl = 0; ktl < 2; ktl++) {
            const int ktg = 2 * c + ktl;
            uint4 ah4 = g_Waf[((size_t)(0 * MT2 + w) * KT2 + ktg) * 32 + lane];
            uint4 al4 = g_Waf[((size_t)(1 * MT2 + w) * KT2 + ktg) * 32 + lane];
            const unsigned* ah = (const unsigned*)&ah4;
            const unsigned* al = (const unsigned*)&al4;
            const uint2* bhb = Bf + ((cur * 2 + 0) * 2 + ktl) * 416 + lane;
            const uint2* blb = Bf + ((cur * 2 + 1) * 2 + ktl) * 416 + lane;
#pragma unroll
            for (int nt = 0; nt < 13; nt++) {
                uint2 bh = bhb[nt * 32];
                uint2 bl = blb[nt * 32];
                mma_bf16(acc[nt], ah, bh);
                mma_bf16(acc[nt], ah, bl);
                mma_bf16(acc[nt], al, bh);
            }
        }
        cpa_wait0();
        __syncthreads();
    }

#pragma unroll
    for (int nt = 0; nt < 13; nt++) {
        int r0 = w * 16 + g;
        int cc = nt * 8 + 2 * t;
        if (r0 < N1) {
            Y1s[r0 * 104 + cc] = fsinh(acc[nt][0]);
            Y1s[r0 * 104 + cc + 1] = fsinh(acc[nt][1]);
        }
        if (r0 + 8 < N1) {
            Y1s[(r0 + 8) * 104 + cc] = fsinh(acc[nt][2]);
            Y1s[(r0 + 8) * 104 + cc + 1] = fsinh(acc[nt][3]);
        }
    }
    __syncthreads();

    for (int e = tid; e < N1 * N2; e += 224) {
        int o = e / 25, p2 = e % 25;
        const float4* yr = (const float4*)(Y1s + o * 104);
        const float4* wr = (const float4*)(W2s + p2 * 100);
        float sum = 0.f;
#pragma unroll
        for (int i = 0; i < 25; i++) {
            float4 a = yr[i], wv = wr[i];
            sum += a.x * wv.x + a.y * wv.y + a.z * wv.z + a.w * wv.w;
        }
        T2t[p2 * 104 + o] = sum;
    }
    __syncthreads();

    for (int e = tid; e < N2 * N2; e += 224) {
        int q = e / 25, p = e % 25;
        const float4* wq = (const float4*)(W2s + q * 100);
        const float4* tp4 = (const float4*)(T2t + p * 104);
        float sum = 0.f;
#pragma unroll
        for (int i = 0; i < 25; i++) {
            float4 a = wq[i], tv = tp4[i];
            sum += a.x * tv.x + a.y * tv.y + a.z * tv.z + a.w * tv.w;
        }
        g_Y2[b * 625 + e] = fsinh(sum);
    }
}

// ---------------- K3: 2-warp CTAs; Jacobi + U log(L) U^T ----------------
__global__ void __launch_bounds__(64) k3_logeig(float* __restrict__ out) {
    __shared__ float As[2][650];
    __shared__ float Vs[2][650];
    __shared__ float Cc[2][13], Sc[2][13];

    const int w = threadIdx.x >> 5, lane = threadIdx.x & 31;
    const int b = blockIdx.x * 2 + w;
    float* A = As[w];
    float* V = Vs[w];
    const float* Y = g_Y2 + b * 625;

    for (int e = lane; e < 625; e += 32) {
        int i = e / 25, j = e % 25;
        A[i * 26 + j] = 0.5f * (Y[e] + Y[j * 25 + i]);
        V[i * 26 + j] = (i == j) ? 1.f : 0.f;
    }
    __syncwarp();

    for (int sw = 0; sw < NSWEEP; sw++) {
        for (int r = 0; r < 25; r++) {
            if (lane >= 1 && lane <= 12) {
                int k = lane;
                int p = r + k; if (p >= 25) p -= 25;
                int q = r + 25 - k; if (q >= 25) q -= 25;
                float app = A[p * 26 + p], aqq = A[q * 26 + q], apq = A[p * 26 + q];
                float c = 1.f, s = 0.f;
                if (fabsf(apq) > 1e-36f) {
                    float tau = (aqq - app) / (2.f * apq);
                    float t = copysignf(1.f, tau) / (fabsf(tau) + sqrtf(1.f + tau * tau));
                    c = rsqrtf(1.f + t * t);
                    s = t * c;
                }
                Cc[w][k] = c;
                Sc[w][k] = s;
            }
            __syncwarp();
            if (lane < 25) {
                const int l = lane;
#pragma unroll
                for (int k = 1; k <= 12; k++) {
                    int p = r + k; if (p >= 25) p -= 25;
                    int q = r + 25 - k; if (q >= 25) q -= 25;
                    float c = Cc[w][k], s = Sc[w][k];
                    float ap = A[p * 26 + l], aq = A[q * 26 + l];
                    A[p * 26 + l] = c * ap - s * aq;
                    A[q * 26 + l] = s * ap + c * aq;
                }
            }
            __syncwarp();
            if (lane < 25) {
                const int l = lane;
#pragma unroll
                for (int k = 1; k <= 12; k++) {
                    int p = r + k; if (p >= 25) p -= 25;
                    int q = r + 25 - k; if (q >= 25) q -= 25;
                    float c = Cc[w][k], s = Sc[w][k];
                    float ap = A[l * 26 + p], aq = A[l * 26 + q];
                    A[l * 26 + p] = c * ap - s * aq;
                    A[l * 26 + q] = s * ap + c * aq;
                    float vp = V[l * 26 + p], vq = V[l * 26 + q];
                    V[l * 26 + p] = c * vp - s * vq;
                    V[l * 26 + q] = s * vp + c * vq;
                }
            }
            __syncwarp();
        }
    }

    __syncwarp();
    float logd[25];
    if (lane < 25) {
        float d = A[lane * 26 + lane];
        A[lane * 26 + lane] = logf(fmaxf(d, EPSV));
    }
    __syncwarp();
#pragma unroll
    for (int k = 0; k < 25; k++) logd[k] = A[k * 26 + k];

    float* O = out + b * 625;
    for (int e = lane; e < 625; e += 32) {
        int i = e / 25, j = e % 25;
        const float* vi = V + i * 26;
        const float* vj = V + j * 26;
        float sum = 0.f;
#pragma unroll
        for (int k = 0; k < 25; k++) sum += vi[k] * logd[k] * vj[k];
        O[e] = sum;
    }
}

// ---------------- launch ----------------
extern "C" void kernel_launch(void* const* d_in, const int* in_sizes, int n_in,
                              void* d_out, int out_size) {
    const float* X  = (const float*)d_in[0];
    const float* W1 = (const float*)d_in[1];
    const float* W2 = (const float*)d_in[2];
    float* out = (float*)d_out;

    static const int k2_smem = 26624 + (2500 + 10400 + 2600) * 4;
    cudaFuncSetAttribute(k1_hmma, cudaFuncAttributeMaxDynamicSharedMemorySize, K1_SMEM);
    cudaFuncSetAttribute(k2_hmma, cudaFuncAttributeMaxDynamicSharedMemorySize, k2_smem);

    k0_wfrag<<<(2 * KTILES * NTILES * 32 + 255) / 256, 256>>>(W1);
    k0_wafrag<<<(2 * MT2 * KT2 * 32 + 255) / 256, 256>>>(W1);
    k_dummy<<<1, 32>>>();
    k1_hmma<<<dim3(3, Bn), 256, K1_SMEM>>>(X);
    k2_hmma<<<Bn, 224, k2_smem>>>(W2);
    k3_logeig<<<Bn / 2, 64>>>(out);
}